// round 12
// baseline (speedup 1.0000x reference)
#include <cuda_runtime.h>
#include <cuda_fp16.h>
#include <math.h>
#include <stdint.h>

// Problem constants
#define B_DIM 16
#define H_DIM 56
#define W_DIM 56
#define C_DIM 512
#define NHEAD 8
#define HD 64
#define WS 4
#define NWIN 3136      // 16 * 14 * 14
#define NTOK 50176     // NWIN * 16
#define SCALE 0.04419417382415922f   // 512^-0.5

// ---------------- scratch (static device globals; no allocation) -----------
__device__ __half g_qkv[(size_t)NTOK * 1536]; // qkv of local branch (fp16)
__device__ __half g_xg[(size_t)NTOK * 512];   // gathered x (fp16)
__device__ __half g_xh[(size_t)NTOK * 512];   // local attention out (fp16)
__device__ __half g_xavg[NWIN * 512];         // pooled window tokens (fp16)
__device__ float  g_yl[NWIN * 512];           // xavg @ H^T (fp32 window add)
__device__ __half g_wqkv[1536 * 512];         // fp16 w_qkv_h
__device__ __half g_wvlT[512 * 512];          // fp16 transpose of w_qkv_l v-part
__device__ __half g_H[512 * 512];             // fp16 H = Wp2 @ Wvl
__device__ __half g_wp1[512 * 512];           // fp16 w_proj[:, :512]
__device__ __half g_wp2[512 * 512];           // fp16 w_proj[:, 512:]
__device__ int    g_rowidx[NTOK];             // gt -> token row in x / out

// ---------------- small helpers --------------------------------------------
__device__ __forceinline__ uint32_t smem_u32(const void* p) {
    uint32_t a;
    asm("{ .reg .u64 t; cvta.to.shared.u64 t, %1; cvt.u32.u64 %0, t; }" : "=r"(a) : "l"(p));
    return a;
}

__device__ __forceinline__ void cpasync16(uint32_t dst, const void* src) {
    asm volatile("cp.async.cg.shared.global [%0], [%1], 16;" :: "r"(dst), "l"(src) : "memory");
}

__device__ __forceinline__ void ldsm_x4(uint32_t r[4], uint32_t addr) {
    asm volatile("ldmatrix.sync.aligned.m8n8.x4.shared.b16 {%0,%1,%2,%3}, [%4];"
                 : "=r"(r[0]), "=r"(r[1]), "=r"(r[2]), "=r"(r[3]) : "r"(addr));
}

__device__ __forceinline__ void ldsm_x4_t(uint32_t r[4], uint32_t addr) {
    asm volatile("ldmatrix.sync.aligned.m8n8.x4.trans.shared.b16 {%0,%1,%2,%3}, [%4];"
                 : "=r"(r[0]), "=r"(r[1]), "=r"(r[2]), "=r"(r[3]) : "r"(addr));
}

__device__ __forceinline__ void mma_fp16(float c[4], const uint32_t a[4], const uint32_t b[2]) {
    asm volatile(
        "mma.sync.aligned.m16n8k16.row.col.f32.f16.f16.f32 "
        "{%0,%1,%2,%3}, {%4,%5,%6,%7}, {%8,%9}, {%0,%1,%2,%3};"
        : "+f"(c[0]), "+f"(c[1]), "+f"(c[2]), "+f"(c[3])
        : "r"(a[0]), "r"(a[1]), "r"(a[2]), "r"(a[3]), "r"(b[0]), "r"(b[1]));
}

__device__ __forceinline__ uint32_t pack_h2(float a, float b) {
    __half2 h = __floats2half2_rn(a, b);
    return *(uint32_t*)&h;
}

// ---------------- fused gather (->fp16) + pooling + rowidx -----------------
__global__ __launch_bounds__(128)
void k_prep_win(const float* __restrict__ x, __half* __restrict__ xg,
                __half* __restrict__ xavg, int* __restrict__ ridx) {
    const int widx = blockIdx.x;
    const int b = widx / 196;
    const int rem = widx % 196;
    const int wh = rem / 14, ww = rem % 14;
    const int c = threadIdx.x * 4;

    if (threadIdx.x < 16) {
        const int t = threadIdx.x;
        const int row = wh * WS + (t >> 2);
        const int col = ww * WS + (t & 3);
        ridx[widx * 16 + t] = (b * H_DIM + row) * W_DIM + col;
    }

    float4 s = make_float4(0.f, 0.f, 0.f, 0.f);
    #pragma unroll
    for (int t = 0; t < 16; t++) {
        const int row = wh * WS + (t >> 2);
        const int col = ww * WS + (t & 3);
        const size_t srow = (size_t)((b * H_DIM + row) * W_DIM + col);
        const float4 v = *(const float4*)(x + srow * C_DIM + c);
        s.x += v.x; s.y += v.y; s.z += v.z; s.w += v.w;
        *(uint2*)(xg + (size_t)(widx * 16 + t) * C_DIM + c) =
            make_uint2(pack_h2(v.x, v.y), pack_h2(v.z, v.w));
    }
    const float inv = 1.0f / 16.0f;
    *(uint2*)(xavg + (size_t)widx * C_DIM + c) =
        make_uint2(pack_h2(s.x * inv, s.y * inv), pack_h2(s.z * inv, s.w * inv));
}

// ---------------- merged weight conversion to fp16 -------------------------
__global__ void k_wprep(const float* __restrict__ wqkvh, const float* __restrict__ wqkvl,
                        const float* __restrict__ wproj,
                        __half* __restrict__ wqkv, __half* __restrict__ wvlT,
                        __half* __restrict__ wp1, __half* __restrict__ wp2) {
    const int total = 196608 + 65536 + 65536;
    for (int i = blockIdx.x * 256 + threadIdx.x; i < total; i += gridDim.x * 256) {
        if (i < 196608) {
            float4 v = *(const float4*)(wqkvh + (size_t)i * 4);
            *(uint2*)(wqkv + (size_t)i * 4) =
                make_uint2(pack_h2(v.x, v.y), pack_h2(v.z, v.w));
        } else if (i < 262144) {
            // transpose write: wvlT[k][n] = w_qkv_l[1024+n][k]
            int j = i - 196608;
            int n = j >> 7, k4 = (j & 127) * 4;
            float4 v = *(const float4*)(wqkvl + (size_t)(1024 + n) * 512 + k4);
            wvlT[(size_t)(k4 + 0) * 512 + n] = __float2half_rn(v.x);
            wvlT[(size_t)(k4 + 1) * 512 + n] = __float2half_rn(v.y);
            wvlT[(size_t)(k4 + 2) * 512 + n] = __float2half_rn(v.z);
            wvlT[(size_t)(k4 + 3) * 512 + n] = __float2half_rn(v.w);
        } else {
            int j = i - 262144;
            int n = j >> 7, k4 = (j & 127) * 4;
            float4 a = *(const float4*)(wproj + (size_t)n * 1024 + k4);
            float4 b = *(const float4*)(wproj + (size_t)n * 1024 + 512 + k4);
            *(uint2*)(wp1 + (size_t)n * 512 + k4) =
                make_uint2(pack_h2(a.x, a.y), pack_h2(a.z, a.w));
            *(uint2*)(wp2 + (size_t)n * 512 + k4) =
                make_uint2(pack_h2(b.x, b.y), pack_h2(b.z, b.w));
        }
    }
}

// ---------------- fp16 tensor GEMM: C = A * B^T ----------------------------
// CTA tile 128x128 with 4 warps (128 threads), warp tile 64x64 (2Mx2N),
// BK=64 halves (128B rows, SW128), 3-stage cp.async pipeline, 2 CTAs/SM.
#define GBM 128
#define GBN 128
#define GBK 64
#define GK  512
#define NSTG (GK / GBK)        // 8 k-slabs
#define ASTG 16384             // 128 rows * 128 B
#define STG_BYTES 32768        // A + B
#define NPIPE 3

__global__ __launch_bounds__(128, 2)
void tc_gemm(const __half* __restrict__ A, const __half* __restrict__ B,
             void* __restrict__ Cv, int ldc,
             const int* __restrict__ cmap, const float* __restrict__ addwin,
             const float* __restrict__ bias, int M, int outHalf) {
    extern __shared__ char smem[];
    const uint32_t sbase = smem_u32(smem);

    const int tid  = threadIdx.x;
    const int warp = tid >> 5;
    const int lane = tid & 31;
    const int g = lane >> 2;
    const int q = lane & 3;
    const int wm = (warp >> 1) * 64;     // 2 warps in M
    const int wn = (warp & 1) * 64;      // 2 warps in N
    const int bm = blockIdx.y * GBM;
    const int bn = blockIdx.x * GBN;

    const int mid = lane >> 3;          // matrix id 0..3
    const int r7  = lane & 7;
    const int aRow0 = wm + (mid & 1) * 8 + r7;       // + t*16
    const int aHalf = (mid >> 1) * 16;               // kb byte offset
    const int bRow0 = wn + (mid >> 1) * 8 + r7;      // + up*16
    const int bHalf = (mid & 1) * 16;

    float acc[4][8][4];
    #pragma unroll
    for (int t = 0; t < 4; t++)
        #pragma unroll
        for (int u = 0; u < 8; u++)
            #pragma unroll
            for (int r = 0; r < 4; r++) acc[t][u][r] = 0.f;

    auto load_stage = [&](int s, int buf) {
        const int k0 = s * GBK;
        const uint32_t ao = sbase + buf * STG_BYTES;
        const uint32_t bo = ao + ASTG;
        #pragma unroll
        for (int i = 0; i < 8; i++) {
            int idx = tid + i * 128;          // 0..1023
            int r = idx >> 3, hc = idx & 7;
            int grow = bm + r; if (grow >= M) grow = M - 1;
            uint32_t off = (uint32_t)(r * 128 + hc * 16);
            cpasync16(ao + (off ^ ((off >> 3) & 0x70)),
                      A + (size_t)grow * GK + k0 + hc * 8);
        }
        #pragma unroll
        for (int i = 0; i < 8; i++) {
            int idx = tid + i * 128;
            int r = idx >> 3, hc = idx & 7;
            uint32_t off = (uint32_t)(r * 128 + hc * 16);
            cpasync16(bo + (off ^ ((off >> 3) & 0x70)),
                      B + (size_t)(bn + r) * GK + k0 + hc * 8);
        }
        asm volatile("cp.async.commit_group;" ::: "memory");
    };

    load_stage(0, 0);
    load_stage(1, 1);
    load_stage(2, 2);

    for (int s = 0; s < NSTG; s++) {
        const int buf = s % NPIPE;
        if (s <= NSTG - 3)      asm volatile("cp.async.wait_group 2;" ::: "memory");
        else if (s == NSTG - 2) asm volatile("cp.async.wait_group 1;" ::: "memory");
        else                    asm volatile("cp.async.wait_group 0;" ::: "memory");
        __syncthreads();

        const uint32_t sA = sbase + buf * STG_BYTES;
        const uint32_t sB = sA + ASTG;

        #pragma unroll
        for (int kk = 0; kk < 4; kk++) {
            const uint32_t acol = (uint32_t)(kk * 32 + aHalf);
            const uint32_t bcol = (uint32_t)(kk * 32 + bHalf);
            uint32_t af[4][4];
            #pragma unroll
            for (int t = 0; t < 4; t++) {
                const uint32_t row = (uint32_t)(aRow0 + t * 16);
                ldsm_x4(af[t], sA + (row << 7) + (((row & 7) << 4) ^ acol));
            }
            uint32_t bf[8][2];
            #pragma unroll
            for (int up = 0; up < 4; up++) {
                uint32_t r4[4];
                const uint32_t row = (uint32_t)(bRow0 + up * 16);
                ldsm_x4(r4, sB + (row << 7) + (((row & 7) << 4) ^ bcol));
                bf[up * 2 + 0][0] = r4[0]; bf[up * 2 + 0][1] = r4[1];
                bf[up * 2 + 1][0] = r4[2]; bf[up * 2 + 1][1] = r4[3];
            }
            #pragma unroll
            for (int t = 0; t < 4; t++)
                #pragma unroll
                for (int u = 0; u < 8; u++)
                    mma_fp16(acc[t][u], af[t], bf[u]);
        }
        __syncthreads();
        if (s + NPIPE < NSTG) load_stage(s + NPIPE, buf);
    }

    // ---- epilogue ----
    #pragma unroll
    for (int t = 0; t < 4; t++) {
        #pragma unroll
        for (int half = 0; half < 2; half++) {
            const int gm = bm + wm + t * 16 + g + half * 8;
            if (gm >= M) continue;
            const size_t orow = cmap ? (size_t)cmap[gm] : (size_t)gm;
            const float* ap = addwin ? addwin + (size_t)(gm >> 4) * 512 : nullptr;
            const int colb = bn + wn + 2 * q;
            #pragma unroll
            for (int u = 0; u < 8; u++) {
                const int col = colb + u * 8;
                float o0 = acc[t][u][half * 2 + 0];
                float o1 = acc[t][u][half * 2 + 1];
                if (ap)   { o0 += ap[col];   o1 += ap[col + 1]; }
                if (bias) { o0 += bias[col]; o1 += bias[col + 1]; }
                if (outHalf) {
                    *(uint32_t*)((__half*)Cv + orow * ldc + col) = pack_h2(o0, o1);
                } else {
                    *(float2*)((float*)Cv + orow * ldc + col) = make_float2(o0, o1);
                }
            }
        }
    }
}

// ---------------- tensor-core window attention -----------------------------
// block = 1 window (256 threads), warp = 1 head. No block-wide syncs.
// smem per warp: 2 swizzled 16x64-half tiles (Q and K; V reuses Q's tile
// after the S-phase ldsm complete). V loaded to registers up front so its
// global reads overlap the QK^T MMAs.
#define AWARP_B 4096                       // bytes per warp (Q + K tiles)
#define ATT_SMEM (8 * AWARP_B)             // 32768 bytes

__global__ __launch_bounds__(256)
void k_attn_tc(const __half* __restrict__ qkv, __half* __restrict__ xh) {
    extern __shared__ char asm_b[];
    const int widx = blockIdx.x;
    const int warp = threadIdx.x >> 5;     // head
    const int lane = threadIdx.x & 31;

    char* sq = asm_b + warp * AWARP_B;     // 2048 B swizzled tile
    char* sk = sq + 2048;

    // stage Q/K to smem (swizzled); V to registers
    const __half* base = qkv + (size_t)widx * 16 * 1536 + warp * 64;
    uint4 vreg[4];
    uint32_t vsw[4];
    #pragma unroll
    for (int i = 0; i < 4; i++) {
        int idx = lane + i * 32;           // 0..127
        int r = idx >> 3, c8 = idx & 7;
        const __half* src = base + (size_t)r * 1536 + c8 * 8;
        uint32_t off = (uint32_t)(r * 128 + c8 * 16);
        uint32_t sw = off ^ ((off >> 3) & 0x70);
        *(uint4*)(sq + sw) = *(const uint4*)(src);
        *(uint4*)(sk + sw) = *(const uint4*)(src + 512);
        vreg[i] = *(const uint4*)(src + 1024);
        vsw[i] = sw;
    }
    __syncwarp();

    const int mid = lane >> 3, r7 = lane & 7;
    const int g = lane >> 2, q = lane & 3;
    const uint32_t sqb = smem_u32(sq), skb = smem_u32(sk);
    const uint32_t arow = (uint32_t)((mid & 1) * 8 + r7);
    const uint32_t acolb = (uint32_t)((mid >> 1) * 16);
    const uint32_t brow = (uint32_t)((mid >> 1) * 8 + r7);
    const uint32_t bcolb = (uint32_t)((mid & 1) * 16);
    const uint32_t axor = (uint32_t)(r7 << 4);   // (row&7)<<4 for both

    // ---- S = Q K^T ----
    float s0[4] = {0.f, 0.f, 0.f, 0.f};
    float s1[4] = {0.f, 0.f, 0.f, 0.f};
    #pragma unroll
    for (int kk = 0; kk < 4; kk++) {
        uint32_t a[4], b[4];
        ldsm_x4(a, sqb + (arow << 7) + ((acolb + kk * 32) ^ axor));
        ldsm_x4(b, skb + (brow << 7) + ((bcolb + kk * 32) ^ axor));
        mma_fp16(s0, a, b);
        mma_fp16(s1, a, b + 2);
    }
    // Q fragments consumed (ldsm is warp-synchronous) -> reuse sq for V
    #pragma unroll
    for (int i = 0; i < 4; i++)
        *(uint4*)(sq + vsw[i]) = vreg[i];

    // ---- softmax (rows g and g+8; deferred normalization) ----
    float e0[4], e1[4], inv[2];
    #pragma unroll
    for (int h2 = 0; h2 < 2; h2++) {
        const int i0 = h2 * 2, i1 = h2 * 2 + 1;
        float a0 = s0[i0] * SCALE, a1 = s0[i1] * SCALE;
        float b0 = s1[i0] * SCALE, b1 = s1[i1] * SCALE;
        float m = fmaxf(fmaxf(a0, a1), fmaxf(b0, b1));
        m = fmaxf(m, __shfl_xor_sync(0xffffffffu, m, 1));
        m = fmaxf(m, __shfl_xor_sync(0xffffffffu, m, 2));
        a0 = expf(a0 - m); a1 = expf(a1 - m);
        b0 = expf(b0 - m); b1 = expf(b1 - m);
        float su = a0 + a1 + b0 + b1;
        su += __shfl_xor_sync(0xffffffffu, su, 1);
        su += __shfl_xor_sync(0xffffffffu, su, 2);
        inv[h2] = __frcp_rn(su);
        e0[i0] = a0; e0[i1] = a1;
        e1[i0] = b0; e1[i1] = b1;
    }

    uint32_t pa[4];
    pa[0] = pack_h2(e0[0], e0[1]);
    pa[1] = pack_h2(e0[2], e0[3]);
    pa[2] = pack_h2(e1[0], e1[1]);
    pa[3] = pack_h2(e1[2], e1[3]);
    __syncwarp();      // V stores visible to all lanes

    // ---- O = P~ V ----  (V now lives in sq)
    float o[8][4];
    #pragma unroll
    for (int u = 0; u < 8; u++)
        #pragma unroll
        for (int r = 0; r < 4; r++) o[u][r] = 0.f;
    #pragma unroll
    for (int nt = 0; nt < 4; nt++) {
        uint32_t b[4];
        ldsm_x4_t(b, sqb + (arow << 7) + ((acolb + nt * 32) ^ axor));
        mma_fp16(o[nt * 2 + 0], pa, b);
        mma_fp16(o[nt * 2 + 1], pa, b + 2);
    }

    __half* dst = xh + (size_t)widx * 16 * 512 + warp * 64;
    #pragma unroll
    for (int u = 0; u < 8; u++) {
        const int col = u * 8 + 2 * q;
        *(uint32_t*)(dst + (size_t)g * 512 + col) =
            pack_h2(o[u][0] * inv[0], o[u][1] * inv[0]);
        *(uint32_t*)(dst + (size_t)(g + 8) * 512 + col) =
            pack_h2(o[u][2] * inv[1], o[u][3] * inv[1]);
    }
}

// ---------------- launch ---------------------------------------------------
#define TC_SMEM (NPIPE * STG_BYTES)   // 98304 bytes

extern "C" void kernel_launch(void* const* d_in, const int* in_sizes, int n_in,
                              void* d_out, int out_size) {
    const float* x        = (const float*)d_in[0];
    const float* w_qkv_h  = (const float*)d_in[1];
    const float* w_qkv_l  = (const float*)d_in[2];
    const float* w_proj   = (const float*)d_in[3];
    const float* b_proj   = (const float*)d_in[4];
    float* out = (float*)d_out;

    __half *qkv, *xg, *xh, *xavg, *wqkv, *wvlT, *Hm, *wp1, *wp2;
    float *yl;
    int* ridx;
    cudaGetSymbolAddress((void**)&qkv,  g_qkv);
    cudaGetSymbolAddress((void**)&xg,   g_xg);
    cudaGetSymbolAddress((void**)&xh,   g_xh);
    cudaGetSymbolAddress((void**)&xavg, g_xavg);
    cudaGetSymbolAddress((void**)&yl,   g_yl);
    cudaGetSymbolAddress((void**)&wqkv, g_wqkv);
    cudaGetSymbolAddress((void**)&wvlT, g_wvlT);
    cudaGetSymbolAddress((void**)&Hm,   g_H);
    cudaGetSymbolAddress((void**)&wp1,  g_wp1);
    cudaGetSymbolAddress((void**)&wp2,  g_wp2);
    cudaGetSymbolAddress((void**)&ridx, g_rowidx);

    cudaFuncSetAttribute(tc_gemm, cudaFuncAttributeMaxDynamicSharedMemorySize, TC_SMEM);
    cudaFuncSetAttribute(k_attn_tc, cudaFuncAttributeMaxDynamicSharedMemorySize, ATT_SMEM);

    // 1. fused gather + pool + rowidx; weights -> fp16 (+ transposed Wvl)
    k_prep_win<<<NWIN, 128>>>(x, xg, xavg, ridx);
    k_wprep<<<1280, 256>>>(w_qkv_h, w_qkv_l, w_proj, wqkv, wvlT, wp1, wp2);

    // 2. H = Wp2 @ Wvl  (tiny 512^3 GEMM; H[i,j] = sum_k wp2[i,k] wvlT[j,k])
    tc_gemm<<<dim3(512 / GBN, 512 / GBM), 128, TC_SMEM>>>(
        wp2, wvlT, Hm, 512, nullptr, nullptr, nullptr, 512, 1);

    // 3. local branch qkv = xg @ w_qkv_h^T -> [NTOK, 1536] fp16  (big GEMM)
    tc_gemm<<<dim3(1536 / GBN, NTOK / GBM), 128, TC_SMEM>>>(
        xg, wqkv, qkv, 1536, nullptr, nullptr, nullptr, NTOK, 1);

    // 4. tensor-core window attention (block = window, warp = head)
    k_attn_tc<<<NWIN, 256, ATT_SMEM>>>(qkv, xh);

    // 5. global branch collapsed: yl = xavg @ H^T  (fp32 out)
    tc_gemm<<<dim3(512 / GBN, (NWIN + GBM - 1) / GBM), 128, TC_SMEM>>>(
        xavg, Hm, yl, 512, nullptr, nullptr, nullptr, NWIN, 0);

    // 6. out = scatter( xh @ Wp1^T + yl[window] + bias )  (fp32 out)
    tc_gemm<<<dim3(512 / GBN, NTOK / GBM), 128, TC_SMEM>>>(
        xh, wp1, out, 512, ridx, yl, b_proj, NTOK, 0);
}

// round 13
// speedup vs baseline: 1.0039x; 1.0039x over previous
#include <cuda_runtime.h>
#include <cuda_fp16.h>
#include <math.h>
#include <stdint.h>

// Problem constants
#define B_DIM 16
#define H_DIM 56
#define W_DIM 56
#define C_DIM 512
#define NHEAD 8
#define HD 64
#define WS 4
#define NWIN 3136      // 16 * 14 * 14
#define NTOK 50176     // NWIN * 16
#define SCALE 0.04419417382415922f   // 512^-0.5

// ---------------- scratch (static device globals; no allocation) -----------
__device__ __half g_qkv[(size_t)NTOK * 1536]; // qkv of local branch (fp16)
__device__ __half g_xg[(size_t)NTOK * 512];   // gathered x (fp16)
__device__ __half g_xh[(size_t)NTOK * 512];   // local attention out (fp16)
__device__ __half g_xavg[NWIN * 512];         // pooled window tokens (fp16)
__device__ __half g_vl[NWIN * 512];           // v of global branch (fp16)
__device__ float  g_yl[NWIN * 512];           // vl @ Wp2^T (fp32 window add)
__device__ __half g_wqkv[1536 * 512];         // fp16 w_qkv_h
__device__ __half g_wvl[512 * 512];           // fp16 w_qkv_l v-part
__device__ __half g_wp1[512 * 512];           // fp16 w_proj[:, :512]
__device__ __half g_wp2[512 * 512];           // fp16 w_proj[:, 512:]
__device__ int    g_rowidx[NTOK];             // gt -> token row in x / out

// ---------------- small helpers --------------------------------------------
__device__ __forceinline__ uint32_t smem_u32(const void* p) {
    uint32_t a;
    asm("{ .reg .u64 t; cvta.to.shared.u64 t, %1; cvt.u32.u64 %0, t; }" : "=r"(a) : "l"(p));
    return a;
}

__device__ __forceinline__ void cpasync16(uint32_t dst, const void* src) {
    asm volatile("cp.async.cg.shared.global [%0], [%1], 16;" :: "r"(dst), "l"(src) : "memory");
}

__device__ __forceinline__ void ldsm_x4(uint32_t r[4], uint32_t addr) {
    asm volatile("ldmatrix.sync.aligned.m8n8.x4.shared.b16 {%0,%1,%2,%3}, [%4];"
                 : "=r"(r[0]), "=r"(r[1]), "=r"(r[2]), "=r"(r[3]) : "r"(addr));
}

__device__ __forceinline__ void ldsm_x4_t(uint32_t r[4], uint32_t addr) {
    asm volatile("ldmatrix.sync.aligned.m8n8.x4.trans.shared.b16 {%0,%1,%2,%3}, [%4];"
                 : "=r"(r[0]), "=r"(r[1]), "=r"(r[2]), "=r"(r[3]) : "r"(addr));
}

__device__ __forceinline__ void mma_fp16(float c[4], const uint32_t a[4], const uint32_t b[2]) {
    asm volatile(
        "mma.sync.aligned.m16n8k16.row.col.f32.f16.f16.f32 "
        "{%0,%1,%2,%3}, {%4,%5,%6,%7}, {%8,%9}, {%0,%1,%2,%3};"
        : "+f"(c[0]), "+f"(c[1]), "+f"(c[2]), "+f"(c[3])
        : "r"(a[0]), "r"(a[1]), "r"(a[2]), "r"(a[3]), "r"(b[0]), "r"(b[1]));
}

__device__ __forceinline__ uint32_t pack_h2(float a, float b) {
    __half2 h = __floats2half2_rn(a, b);
    return *(uint32_t*)&h;
}

// ---------------- fused prep: gather + pool + rowidx + weight convert ------
// blocks [0, NWIN): one window each (gather -> fp16, pool, rowidx)
// blocks [NWIN, NWIN+WPREP_BLKS): strided fp16 conversion of all weights
#define WPREP_BLKS 320
#define WTOTAL (196608 + 65536 + 65536)    // float4 units

__global__ __launch_bounds__(128)
void k_prep(const float* __restrict__ x,
            const float* __restrict__ wqkvh, const float* __restrict__ wqkvl,
            const float* __restrict__ wproj,
            __half* __restrict__ xg, __half* __restrict__ xavg,
            int* __restrict__ ridx,
            __half* __restrict__ wqkv, __half* __restrict__ wvl,
            __half* __restrict__ wp1, __half* __restrict__ wp2) {
    if (blockIdx.x >= NWIN) {
        // ---- weight conversion path ----
        const int base = (blockIdx.x - NWIN) * 128 + threadIdx.x;
        for (int i = base; i < WTOTAL; i += WPREP_BLKS * 128) {
            if (i < 196608) {
                float4 v = *(const float4*)(wqkvh + (size_t)i * 4);
                *(uint2*)(wqkv + (size_t)i * 4) =
                    make_uint2(pack_h2(v.x, v.y), pack_h2(v.z, v.w));
            } else if (i < 262144) {
                int j = i - 196608;
                float4 v = *(const float4*)(wqkvl + (size_t)(1024 * 512) + (size_t)j * 4);
                *(uint2*)(wvl + (size_t)j * 4) =
                    make_uint2(pack_h2(v.x, v.y), pack_h2(v.z, v.w));
            } else {
                int j = i - 262144;
                int n = j >> 7, k4 = (j & 127) * 4;
                float4 a = *(const float4*)(wproj + (size_t)n * 1024 + k4);
                float4 b = *(const float4*)(wproj + (size_t)n * 1024 + 512 + k4);
                *(uint2*)(wp1 + (size_t)n * 512 + k4) =
                    make_uint2(pack_h2(a.x, a.y), pack_h2(a.z, a.w));
                *(uint2*)(wp2 + (size_t)n * 512 + k4) =
                    make_uint2(pack_h2(b.x, b.y), pack_h2(b.z, b.w));
            }
        }
        return;
    }

    // ---- window path ----
    const int widx = blockIdx.x;
    const int b = widx / 196;
    const int rem = widx % 196;
    const int wh = rem / 14, ww = rem % 14;
    const int c = threadIdx.x * 4;

    if (threadIdx.x < 16) {
        const int t = threadIdx.x;
        const int row = wh * WS + (t >> 2);
        const int col = ww * WS + (t & 3);
        ridx[widx * 16 + t] = (b * H_DIM + row) * W_DIM + col;
    }

    float4 s = make_float4(0.f, 0.f, 0.f, 0.f);
    #pragma unroll
    for (int t = 0; t < 16; t++) {
        const int row = wh * WS + (t >> 2);
        const int col = ww * WS + (t & 3);
        const size_t srow = (size_t)((b * H_DIM + row) * W_DIM + col);
        const float4 v = *(const float4*)(x + srow * C_DIM + c);
        s.x += v.x; s.y += v.y; s.z += v.z; s.w += v.w;
        *(uint2*)(xg + (size_t)(widx * 16 + t) * C_DIM + c) =
            make_uint2(pack_h2(v.x, v.y), pack_h2(v.z, v.w));
    }
    const float inv = 1.0f / 16.0f;
    *(uint2*)(xavg + (size_t)widx * C_DIM + c) =
        make_uint2(pack_h2(s.x * inv, s.y * inv), pack_h2(s.z * inv, s.w * inv));
}

// ---------------- fp16 tensor GEMM: C = A * B^T ----------------------------
// CTA tile 128x128 with 4 warps (128 threads), warp tile 64x64 (2Mx2N),
// BK=64 halves (128B rows, SW128), 3-stage cp.async pipeline, 2 CTAs/SM.
#define GBM 128
#define GBN 128
#define GBK 64
#define GK  512
#define NSTG (GK / GBK)        // 8 k-slabs
#define ASTG 16384             // 128 rows * 128 B
#define STG_BYTES 32768        // A + B
#define NPIPE 3

__global__ __launch_bounds__(128, 2)
void tc_gemm(const __half* __restrict__ A, const __half* __restrict__ B,
             void* __restrict__ Cv, int ldc,
             const int* __restrict__ cmap, const float* __restrict__ addwin,
             const float* __restrict__ bias, int M, int outHalf) {
    extern __shared__ char smem[];
    const uint32_t sbase = smem_u32(smem);

    const int tid  = threadIdx.x;
    const int warp = tid >> 5;
    const int lane = tid & 31;
    const int g = lane >> 2;
    const int q = lane & 3;
    const int wm = (warp >> 1) * 64;     // 2 warps in M
    const int wn = (warp & 1) * 64;      // 2 warps in N
    const int bm = blockIdx.y * GBM;
    const int bn = blockIdx.x * GBN;

    const int mid = lane >> 3;          // matrix id 0..3
    const int r7  = lane & 7;
    const int aRow0 = wm + (mid & 1) * 8 + r7;       // + t*16
    const int aHalf = (mid >> 1) * 16;               // kb byte offset
    const int bRow0 = wn + (mid >> 1) * 8 + r7;      // + up*16
    const int bHalf = (mid & 1) * 16;

    float acc[4][8][4];
    #pragma unroll
    for (int t = 0; t < 4; t++)
        #pragma unroll
        for (int u = 0; u < 8; u++)
            #pragma unroll
            for (int r = 0; r < 4; r++) acc[t][u][r] = 0.f;

    auto load_stage = [&](int s, int buf) {
        const int k0 = s * GBK;
        const uint32_t ao = sbase + buf * STG_BYTES;
        const uint32_t bo = ao + ASTG;
        #pragma unroll
        for (int i = 0; i < 8; i++) {
            int idx = tid + i * 128;          // 0..1023
            int r = idx >> 3, hc = idx & 7;
            int grow = bm + r; if (grow >= M) grow = M - 1;
            uint32_t off = (uint32_t)(r * 128 + hc * 16);
            cpasync16(ao + (off ^ ((off >> 3) & 0x70)),
                      A + (size_t)grow * GK + k0 + hc * 8);
        }
        #pragma unroll
        for (int i = 0; i < 8; i++) {
            int idx = tid + i * 128;
            int r = idx >> 3, hc = idx & 7;
            uint32_t off = (uint32_t)(r * 128 + hc * 16);
            cpasync16(bo + (off ^ ((off >> 3) & 0x70)),
                      B + (size_t)(bn + r) * GK + k0 + hc * 8);
        }
        asm volatile("cp.async.commit_group;" ::: "memory");
    };

    load_stage(0, 0);
    load_stage(1, 1);
    load_stage(2, 2);

    for (int s = 0; s < NSTG; s++) {
        const int buf = s % NPIPE;
        if (s <= NSTG - 3)      asm volatile("cp.async.wait_group 2;" ::: "memory");
        else if (s == NSTG - 2) asm volatile("cp.async.wait_group 1;" ::: "memory");
        else                    asm volatile("cp.async.wait_group 0;" ::: "memory");
        __syncthreads();

        const uint32_t sA = sbase + buf * STG_BYTES;
        const uint32_t sB = sA + ASTG;

        #pragma unroll
        for (int kk = 0; kk < 4; kk++) {
            const uint32_t acol = (uint32_t)(kk * 32 + aHalf);
            const uint32_t bcol = (uint32_t)(kk * 32 + bHalf);
            uint32_t af[4][4];
            #pragma unroll
            for (int t = 0; t < 4; t++) {
                const uint32_t row = (uint32_t)(aRow0 + t * 16);
                ldsm_x4(af[t], sA + (row << 7) + (((row & 7) << 4) ^ acol));
            }
            uint32_t bf[8][2];
            #pragma unroll
            for (int up = 0; up < 4; up++) {
                uint32_t r4[4];
                const uint32_t row = (uint32_t)(bRow0 + up * 16);
                ldsm_x4(r4, sB + (row << 7) + (((row & 7) << 4) ^ bcol));
                bf[up * 2 + 0][0] = r4[0]; bf[up * 2 + 0][1] = r4[1];
                bf[up * 2 + 1][0] = r4[2]; bf[up * 2 + 1][1] = r4[3];
            }
            #pragma unroll
            for (int t = 0; t < 4; t++)
                #pragma unroll
                for (int u = 0; u < 8; u++)
                    mma_fp16(acc[t][u], af[t], bf[u]);
        }
        __syncthreads();
        if (s + NPIPE < NSTG) load_stage(s + NPIPE, buf);
    }

    // ---- epilogue ----
    #pragma unroll
    for (int t = 0; t < 4; t++) {
        #pragma unroll
        for (int half = 0; half < 2; half++) {
            const int gm = bm + wm + t * 16 + g + half * 8;
            if (gm >= M) continue;
            const size_t orow = cmap ? (size_t)cmap[gm] : (size_t)gm;
            const float* ap = addwin ? addwin + (size_t)(gm >> 4) * 512 : nullptr;
            const int colb = bn + wn + 2 * q;
            #pragma unroll
            for (int u = 0; u < 8; u++) {
                const int col = colb + u * 8;
                float o0 = acc[t][u][half * 2 + 0];
                float o1 = acc[t][u][half * 2 + 1];
                if (ap)   { o0 += ap[col];   o1 += ap[col + 1]; }
                if (bias) { o0 += bias[col]; o1 += bias[col + 1]; }
                if (outHalf) {
                    *(uint32_t*)((__half*)Cv + orow * ldc + col) = pack_h2(o0, o1);
                } else {
                    *(float2*)((float*)Cv + orow * ldc + col) = make_float2(o0, o1);
                }
            }
        }
    }
}

// ---------------- tensor-core window attention -----------------------------
// block = 1 window (256 threads), warp = 1 head. No block-wide syncs.
// smem per warp: 2 swizzled 16x64-half tiles (Q and K; V reuses Q's tile
// after the S-phase ldsm complete). V loaded to registers up front so its
// global reads overlap the QK^T MMAs.
#define AWARP_B 4096                       // bytes per warp (Q + K tiles)
#define ATT_SMEM (8 * AWARP_B)             // 32768 bytes

__global__ __launch_bounds__(256)
void k_attn_tc(const __half* __restrict__ qkv, __half* __restrict__ xh) {
    extern __shared__ char asm_b[];
    const int widx = blockIdx.x;
    const int warp = threadIdx.x >> 5;     // head
    const int lane = threadIdx.x & 31;

    char* sq = asm_b + warp * AWARP_B;     // 2048 B swizzled tile
    char* sk = sq + 2048;

    // stage Q/K to smem (swizzled); V to registers
    const __half* base = qkv + (size_t)widx * 16 * 1536 + warp * 64;
    uint4 vreg[4];
    uint32_t vsw[4];
    #pragma unroll
    for (int i = 0; i < 4; i++) {
        int idx = lane + i * 32;           // 0..127
        int r = idx >> 3, c8 = idx & 7;
        const __half* src = base + (size_t)r * 1536 + c8 * 8;
        uint32_t off = (uint32_t)(r * 128 + c8 * 16);
        uint32_t sw = off ^ ((off >> 3) & 0x70);
        *(uint4*)(sq + sw) = *(const uint4*)(src);
        *(uint4*)(sk + sw) = *(const uint4*)(src + 512);
        vreg[i] = *(const uint4*)(src + 1024);
        vsw[i] = sw;
    }
    __syncwarp();

    const int mid = lane >> 3, r7 = lane & 7;
    const int g = lane >> 2, q = lane & 3;
    const uint32_t sqb = smem_u32(sq), skb = smem_u32(sk);
    const uint32_t arow = (uint32_t)((mid & 1) * 8 + r7);
    const uint32_t acolb = (uint32_t)((mid >> 1) * 16);
    const uint32_t brow = (uint32_t)((mid >> 1) * 8 + r7);
    const uint32_t bcolb = (uint32_t)((mid & 1) * 16);
    const uint32_t axor = (uint32_t)(r7 << 4);   // (row&7)<<4 for both

    // ---- S = Q K^T ----
    float s0[4] = {0.f, 0.f, 0.f, 0.f};
    float s1[4] = {0.f, 0.f, 0.f, 0.f};
    #pragma unroll
    for (int kk = 0; kk < 4; kk++) {
        uint32_t a[4], b[4];
        ldsm_x4(a, sqb + (arow << 7) + ((acolb + kk * 32) ^ axor));
        ldsm_x4(b, skb + (brow << 7) + ((bcolb + kk * 32) ^ axor));
        mma_fp16(s0, a, b);
        mma_fp16(s1, a, b + 2);
    }
    // Q fragments consumed (ldsm is warp-synchronous) -> reuse sq for V
    #pragma unroll
    for (int i = 0; i < 4; i++)
        *(uint4*)(sq + vsw[i]) = vreg[i];

    // ---- softmax (rows g and g+8; deferred normalization) ----
    float e0[4], e1[4], inv[2];
    #pragma unroll
    for (int h2 = 0; h2 < 2; h2++) {
        const int i0 = h2 * 2, i1 = h2 * 2 + 1;
        float a0 = s0[i0] * SCALE, a1 = s0[i1] * SCALE;
        float b0 = s1[i0] * SCALE, b1 = s1[i1] * SCALE;
        float m = fmaxf(fmaxf(a0, a1), fmaxf(b0, b1));
        m = fmaxf(m, __shfl_xor_sync(0xffffffffu, m, 1));
        m = fmaxf(m, __shfl_xor_sync(0xffffffffu, m, 2));
        a0 = expf(a0 - m); a1 = expf(a1 - m);
        b0 = expf(b0 - m); b1 = expf(b1 - m);
        float su = a0 + a1 + b0 + b1;
        su += __shfl_xor_sync(0xffffffffu, su, 1);
        su += __shfl_xor_sync(0xffffffffu, su, 2);
        inv[h2] = __frcp_rn(su);
        e0[i0] = a0; e0[i1] = a1;
        e1[i0] = b0; e1[i1] = b1;
    }

    uint32_t pa[4];
    pa[0] = pack_h2(e0[0], e0[1]);
    pa[1] = pack_h2(e0[2], e0[3]);
    pa[2] = pack_h2(e1[0], e1[1]);
    pa[3] = pack_h2(e1[2], e1[3]);
    __syncwarp();      // V stores visible to all lanes

    // ---- O = P~ V ----  (V now lives in sq)
    float o[8][4];
    #pragma unroll
    for (int u = 0; u < 8; u++)
        #pragma unroll
        for (int r = 0; r < 4; r++) o[u][r] = 0.f;
    #pragma unroll
    for (int nt = 0; nt < 4; nt++) {
        uint32_t b[4];
        ldsm_x4_t(b, sqb + (arow << 7) + ((acolb + nt * 32) ^ axor));
        mma_fp16(o[nt * 2 + 0], pa, b);
        mma_fp16(o[nt * 2 + 1], pa, b + 2);
    }

    __half* dst = xh + (size_t)widx * 16 * 512 + warp * 64;
    #pragma unroll
    for (int u = 0; u < 8; u++) {
        const int col = u * 8 + 2 * q;
        *(uint32_t*)(dst + (size_t)g * 512 + col) =
            pack_h2(o[u][0] * inv[0], o[u][1] * inv[0]);
        *(uint32_t*)(dst + (size_t)(g + 8) * 512 + col) =
            pack_h2(o[u][2] * inv[1], o[u][3] * inv[1]);
    }
}

// ---------------- launch ---------------------------------------------------
#define TC_SMEM (NPIPE * STG_BYTES)   // 98304 bytes

extern "C" void kernel_launch(void* const* d_in, const int* in_sizes, int n_in,
                              void* d_out, int out_size) {
    const float* x        = (const float*)d_in[0];
    const float* w_qkv_h  = (const float*)d_in[1];
    const float* w_qkv_l  = (const float*)d_in[2];
    const float* w_proj   = (const float*)d_in[3];
    const float* b_proj   = (const float*)d_in[4];
    float* out = (float*)d_out;

    __half *qkv, *xg, *xh, *xavg, *vl, *wqkv, *wvl, *wp1, *wp2;
    float *yl;
    int* ridx;
    cudaGetSymbolAddress((void**)&qkv,  g_qkv);
    cudaGetSymbolAddress((void**)&xg,   g_xg);
    cudaGetSymbolAddress((void**)&xh,   g_xh);
    cudaGetSymbolAddress((void**)&xavg, g_xavg);
    cudaGetSymbolAddress((void**)&vl,   g_vl);
    cudaGetSymbolAddress((void**)&yl,   g_yl);
    cudaGetSymbolAddress((void**)&wqkv, g_wqkv);
    cudaGetSymbolAddress((void**)&wvl,  g_wvl);
    cudaGetSymbolAddress((void**)&wp1,  g_wp1);
    cudaGetSymbolAddress((void**)&wp2,  g_wp2);
    cudaGetSymbolAddress((void**)&ridx, g_rowidx);

    cudaFuncSetAttribute(tc_gemm, cudaFuncAttributeMaxDynamicSharedMemorySize, TC_SMEM);
    cudaFuncSetAttribute(k_attn_tc, cudaFuncAttributeMaxDynamicSharedMemorySize, ATT_SMEM);

    // 1. fused prep: gather + pool + rowidx + weight conversion (one launch)
    k_prep<<<NWIN + WPREP_BLKS, 128>>>(x, w_qkv_h, w_qkv_l, w_proj,
                                       xg, xavg, ridx, wqkv, wvl, wp1, wp2);

    // 2. local branch qkv = xg @ w_qkv_h^T -> [NTOK, 1536] fp16  (big GEMM)
    tc_gemm<<<dim3(1536 / GBN, NTOK / GBM), 128, TC_SMEM>>>(
        xg, wqkv, qkv, 1536, nullptr, nullptr, nullptr, NTOK, 1);

    // 3. tensor-core window attention (block = window, warp = head)
    k_attn_tc<<<NWIN, 256, ATT_SMEM>>>(qkv, xh);

    // 4. global branch (softmax over 1 token == identity): vl = xavg @ Wv_l^T
    tc_gemm<<<dim3(512 / GBN, (NWIN + GBM - 1) / GBM), 128, TC_SMEM>>>(
        xavg, wvl, vl, 512, nullptr, nullptr, nullptr, NWIN, 1);

    // 5. yl = vl @ Wp2^T  (fp32 out)
    tc_gemm<<<dim3(512 / GBN, (NWIN + GBM - 1) / GBM), 128, TC_SMEM>>>(
        vl, wp2, yl, 512, nullptr, nullptr, nullptr, NWIN, 0);

    // 6. out = scatter( xh @ Wp1^T + yl[window] + bias )  (fp32 out)
    tc_gemm<<<dim3(512 / GBN, NTOK / GBM), 128, TC_SMEM>>>(
        xh, wp1, out, 512, ridx, yl, b_proj, NTOK, 0);
}

// round 14
// speedup vs baseline: 1.0115x; 1.0075x over previous
#include <cuda_runtime.h>
#include <cuda_fp16.h>
#include <math.h>
#include <stdint.h>

// Problem constants
#define B_DIM 16
#define H_DIM 56
#define W_DIM 56
#define C_DIM 512
#define NHEAD 8
#define HD 64
#define WS 4
#define NWIN 3136      // 16 * 14 * 14
#define NTOK 50176     // NWIN * 16
#define SCALE 0.04419417382415922f   // 512^-0.5

// ---------------- scratch (static device globals; no allocation) -----------
__device__ __half g_qkv[(size_t)NTOK * 1536]; // qkv of local branch (fp16)
__device__ __half g_xg[(size_t)NTOK * 512];   // gathered x (fp16)
__device__ __half g_xh[(size_t)NTOK * 512];   // local attention out (fp16)
__device__ __half g_xavg[NWIN * 512];         // pooled window tokens (fp16)
__device__ __half g_vl[NWIN * 512];           // v of global branch (fp16)
__device__ float  g_yl[NWIN * 512];           // vl @ Wp2^T (fp32 window add)
__device__ __half g_wqkv[1536 * 512];         // fp16 w_qkv_h
__device__ __half g_wvl[512 * 512];           // fp16 w_qkv_l v-part
__device__ __half g_wp1[512 * 512];           // fp16 w_proj[:, :512]
__device__ __half g_wp2[512 * 512];           // fp16 w_proj[:, 512:]
__device__ int    g_rowidx[NTOK];             // gt -> token row in x / out

// ---------------- small helpers --------------------------------------------
__device__ __forceinline__ uint32_t smem_u32(const void* p) {
    uint32_t a;
    asm("{ .reg .u64 t; cvta.to.shared.u64 t, %1; cvt.u32.u64 %0, t; }" : "=r"(a) : "l"(p));
    return a;
}

__device__ __forceinline__ void cpasync16(uint32_t dst, const void* src) {
    asm volatile("cp.async.cg.shared.global [%0], [%1], 16;" :: "r"(dst), "l"(src) : "memory");
}

__device__ __forceinline__ void ldsm_x4(uint32_t r[4], uint32_t addr) {
    asm volatile("ldmatrix.sync.aligned.m8n8.x4.shared.b16 {%0,%1,%2,%3}, [%4];"
                 : "=r"(r[0]), "=r"(r[1]), "=r"(r[2]), "=r"(r[3]) : "r"(addr));
}

__device__ __forceinline__ void ldsm_x4_t(uint32_t r[4], uint32_t addr) {
    asm volatile("ldmatrix.sync.aligned.m8n8.x4.trans.shared.b16 {%0,%1,%2,%3}, [%4];"
                 : "=r"(r[0]), "=r"(r[1]), "=r"(r[2]), "=r"(r[3]) : "r"(addr));
}

__device__ __forceinline__ void mma_fp16(float c[4], const uint32_t a[4], const uint32_t b[2]) {
    asm volatile(
        "mma.sync.aligned.m16n8k16.row.col.f32.f16.f16.f32 "
        "{%0,%1,%2,%3}, {%4,%5,%6,%7}, {%8,%9}, {%0,%1,%2,%3};"
        : "+f"(c[0]), "+f"(c[1]), "+f"(c[2]), "+f"(c[3])
        : "r"(a[0]), "r"(a[1]), "r"(a[2]), "r"(a[3]), "r"(b[0]), "r"(b[1]));
}

__device__ __forceinline__ uint32_t pack_h2(float a, float b) {
    __half2 h = __floats2half2_rn(a, b);
    return *(uint32_t*)&h;
}

// ---------------- fused prep: gather + pool + rowidx + weight convert ------
#define WPREP_BLKS 320
#define WTOTAL (196608 + 65536 + 65536)    // float4 units

__global__ __launch_bounds__(128)
void k_prep(const float* __restrict__ x,
            const float* __restrict__ wqkvh, const float* __restrict__ wqkvl,
            const float* __restrict__ wproj,
            __half* __restrict__ xg, __half* __restrict__ xavg,
            int* __restrict__ ridx,
            __half* __restrict__ wqkv, __half* __restrict__ wvl,
            __half* __restrict__ wp1, __half* __restrict__ wp2) {
    if (blockIdx.x >= NWIN) {
        const int base = (blockIdx.x - NWIN) * 128 + threadIdx.x;
        for (int i = base; i < WTOTAL; i += WPREP_BLKS * 128) {
            if (i < 196608) {
                float4 v = *(const float4*)(wqkvh + (size_t)i * 4);
                *(uint2*)(wqkv + (size_t)i * 4) =
                    make_uint2(pack_h2(v.x, v.y), pack_h2(v.z, v.w));
            } else if (i < 262144) {
                int j = i - 196608;
                float4 v = *(const float4*)(wqkvl + (size_t)(1024 * 512) + (size_t)j * 4);
                *(uint2*)(wvl + (size_t)j * 4) =
                    make_uint2(pack_h2(v.x, v.y), pack_h2(v.z, v.w));
            } else {
                int j = i - 262144;
                int n = j >> 7, k4 = (j & 127) * 4;
                float4 a = *(const float4*)(wproj + (size_t)n * 1024 + k4);
                float4 b = *(const float4*)(wproj + (size_t)n * 1024 + 512 + k4);
                *(uint2*)(wp1 + (size_t)n * 512 + k4) =
                    make_uint2(pack_h2(a.x, a.y), pack_h2(a.z, a.w));
                *(uint2*)(wp2 + (size_t)n * 512 + k4) =
                    make_uint2(pack_h2(b.x, b.y), pack_h2(b.z, b.w));
            }
        }
        return;
    }

    const int widx = blockIdx.x;
    const int b = widx / 196;
    const int rem = widx % 196;
    const int wh = rem / 14, ww = rem % 14;
    const int c = threadIdx.x * 4;

    if (threadIdx.x < 16) {
        const int t = threadIdx.x;
        const int row = wh * WS + (t >> 2);
        const int col = ww * WS + (t & 3);
        ridx[widx * 16 + t] = (b * H_DIM + row) * W_DIM + col;
    }

    float4 s = make_float4(0.f, 0.f, 0.f, 0.f);
    #pragma unroll
    for (int t = 0; t < 16; t++) {
        const int row = wh * WS + (t >> 2);
        const int col = ww * WS + (t & 3);
        const size_t srow = (size_t)((b * H_DIM + row) * W_DIM + col);
        const float4 v = *(const float4*)(x + srow * C_DIM + c);
        s.x += v.x; s.y += v.y; s.z += v.z; s.w += v.w;
        *(uint2*)(xg + (size_t)(widx * 16 + t) * C_DIM + c) =
            make_uint2(pack_h2(v.x, v.y), pack_h2(v.z, v.w));
    }
    const float inv = 1.0f / 16.0f;
    *(uint2*)(xavg + (size_t)widx * C_DIM + c) =
        make_uint2(pack_h2(s.x * inv, s.y * inv), pack_h2(s.z * inv, s.w * inv));
}

// ---------------- fp16 tensor GEMM body: C = A * B^T -----------------------
// CTA tile 128x128 with 4 warps (128 threads), warp tile 64x64 (2Mx2N),
// BK=64 halves (128B rows, SW128), 3-stage cp.async pipeline.
#define GBM 128
#define GBN 128
#define GBK 64
#define GK  512
#define NSTG (GK / GBK)        // 8 k-slabs
#define ASTG 16384             // 128 rows * 128 B
#define STG_BYTES 32768        // A + B
#define NPIPE 3

__device__ __forceinline__
void gemm_body(const __half* __restrict__ A, const __half* __restrict__ B,
               void* __restrict__ Cv, int ldc,
               const int* __restrict__ cmap, const float* __restrict__ addwin,
               const float* __restrict__ bias, int M, int outHalf,
               int bm, int bn, char* smem) {
    const uint32_t sbase = smem_u32(smem);

    const int tid  = threadIdx.x;
    const int warp = tid >> 5;
    const int lane = tid & 31;
    const int g = lane >> 2;
    const int q = lane & 3;
    const int wm = (warp >> 1) * 64;     // 2 warps in M
    const int wn = (warp & 1) * 64;      // 2 warps in N

    const int mid = lane >> 3;          // matrix id 0..3
    const int r7  = lane & 7;
    const int aRow0 = wm + (mid & 1) * 8 + r7;       // + t*16
    const int aHalf = (mid >> 1) * 16;               // kb byte offset
    const int bRow0 = wn + (mid >> 1) * 8 + r7;      // + up*16
    const int bHalf = (mid & 1) * 16;

    float acc[4][8][4];
    #pragma unroll
    for (int t = 0; t < 4; t++)
        #pragma unroll
        for (int u = 0; u < 8; u++)
            #pragma unroll
            for (int r = 0; r < 4; r++) acc[t][u][r] = 0.f;

    auto load_stage = [&](int s, int buf) {
        const int k0 = s * GBK;
        const uint32_t ao = sbase + buf * STG_BYTES;
        const uint32_t bo = ao + ASTG;
        #pragma unroll
        for (int i = 0; i < 8; i++) {
            int idx = tid + i * 128;          // 0..1023
            int r = idx >> 3, hc = idx & 7;
            int grow = bm + r; if (grow >= M) grow = M - 1;
            uint32_t off = (uint32_t)(r * 128 + hc * 16);
            cpasync16(ao + (off ^ ((off >> 3) & 0x70)),
                      A + (size_t)grow * GK + k0 + hc * 8);
        }
        #pragma unroll
        for (int i = 0; i < 8; i++) {
            int idx = tid + i * 128;
            int r = idx >> 3, hc = idx & 7;
            uint32_t off = (uint32_t)(r * 128 + hc * 16);
            cpasync16(bo + (off ^ ((off >> 3) & 0x70)),
                      B + (size_t)(bn + r) * GK + k0 + hc * 8);
        }
        asm volatile("cp.async.commit_group;" ::: "memory");
    };

    load_stage(0, 0);
    load_stage(1, 1);
    load_stage(2, 2);

    for (int s = 0; s < NSTG; s++) {
        const int buf = s % NPIPE;
        if (s <= NSTG - 3)      asm volatile("cp.async.wait_group 2;" ::: "memory");
        else if (s == NSTG - 2) asm volatile("cp.async.wait_group 1;" ::: "memory");
        else                    asm volatile("cp.async.wait_group 0;" ::: "memory");
        __syncthreads();

        const uint32_t sA = sbase + buf * STG_BYTES;
        const uint32_t sB = sA + ASTG;

        #pragma unroll
        for (int kk = 0; kk < 4; kk++) {
            const uint32_t acol = (uint32_t)(kk * 32 + aHalf);
            const uint32_t bcol = (uint32_t)(kk * 32 + bHalf);
            uint32_t af[4][4];
            #pragma unroll
            for (int t = 0; t < 4; t++) {
                const uint32_t row = (uint32_t)(aRow0 + t * 16);
                ldsm_x4(af[t], sA + (row << 7) + (((row & 7) << 4) ^ acol));
            }
            uint32_t bf[8][2];
            #pragma unroll
            for (int up = 0; up < 4; up++) {
                uint32_t r4[4];
                const uint32_t row = (uint32_t)(bRow0 + up * 16);
                ldsm_x4(r4, sB + (row << 7) + (((row & 7) << 4) ^ bcol));
                bf[up * 2 + 0][0] = r4[0]; bf[up * 2 + 0][1] = r4[1];
                bf[up * 2 + 1][0] = r4[2]; bf[up * 2 + 1][1] = r4[3];
            }
            #pragma unroll
            for (int t = 0; t < 4; t++)
                #pragma unroll
                for (int u = 0; u < 8; u++)
                    mma_fp16(acc[t][u], af[t], bf[u]);
        }
        __syncthreads();
        if (s + NPIPE < NSTG) load_stage(s + NPIPE, buf);
    }

    // ---- epilogue ----
    #pragma unroll
    for (int t = 0; t < 4; t++) {
        #pragma unroll
        for (int half = 0; half < 2; half++) {
            const int gm = bm + wm + t * 16 + g + half * 8;
            if (gm >= M) continue;
            const size_t orow = cmap ? (size_t)cmap[gm] : (size_t)gm;
            const float* ap = addwin ? addwin + (size_t)(gm >> 4) * 512 : nullptr;
            const int colb = bn + wn + 2 * q;
            #pragma unroll
            for (int u = 0; u < 8; u++) {
                const int col = colb + u * 8;
                float o0 = acc[t][u][half * 2 + 0];
                float o1 = acc[t][u][half * 2 + 1];
                if (ap)   { o0 += ap[col];   o1 += ap[col + 1]; }
                if (bias) { o0 += bias[col]; o1 += bias[col + 1]; }
                if (outHalf) {
                    *(uint32_t*)((__half*)Cv + orow * ldc + col) = pack_h2(o0, o1);
                } else {
                    *(float2*)((float*)Cv + orow * ldc + col) = make_float2(o0, o1);
                }
            }
        }
    }
}

// standard single-task wrapper
__global__ __launch_bounds__(128, 2)
void tc_gemm(const __half* __restrict__ A, const __half* __restrict__ B,
             void* __restrict__ Cv, int ldc,
             const int* __restrict__ cmap, const float* __restrict__ addwin,
             const float* __restrict__ bias, int M, int outHalf) {
    extern __shared__ char smem[];
    gemm_body(A, B, Cv, ldc, cmap, addwin, bias, M, outHalf,
              blockIdx.y * GBM, blockIdx.x * GBN, smem);
}

// dual-task wrapper: rows [0, ySplit) -> task 1; rows >= ySplit -> task 2
// (task 2 uses only blockIdx.x < x2lim)
__global__ __launch_bounds__(128, 2)
void tc_gemm_dual(const __half* __restrict__ A1, const __half* __restrict__ B1,
                  void* __restrict__ C1, int ldc1, int M1, int outHalf1,
                  const __half* __restrict__ A2, const __half* __restrict__ B2,
                  void* __restrict__ C2, int ldc2, int M2, int outHalf2,
                  int ySplit, int x2lim) {
    extern __shared__ char smem[];
    if ((int)blockIdx.y < ySplit) {
        gemm_body(A1, B1, C1, ldc1, nullptr, nullptr, nullptr, M1, outHalf1,
                  blockIdx.y * GBM, blockIdx.x * GBN, smem);
    } else {
        if ((int)blockIdx.x >= x2lim) return;
        gemm_body(A2, B2, C2, ldc2, nullptr, nullptr, nullptr, M2, outHalf2,
                  (blockIdx.y - ySplit) * GBM, blockIdx.x * GBN, smem);
    }
}

// ---------------- tensor-core window attention -----------------------------
// block = 1 window (256 threads), warp = 1 head. No block-wide syncs.
#define AWARP_B 4096                       // bytes per warp (Q + K tiles)
#define ATT_SMEM (8 * AWARP_B)             // 32768 bytes

__global__ __launch_bounds__(256)
void k_attn_tc(const __half* __restrict__ qkv, __half* __restrict__ xh) {
    extern __shared__ char asm_b[];
    const int widx = blockIdx.x;
    const int warp = threadIdx.x >> 5;     // head
    const int lane = threadIdx.x & 31;

    char* sq = asm_b + warp * AWARP_B;     // 2048 B swizzled tile
    char* sk = sq + 2048;

    const __half* base = qkv + (size_t)widx * 16 * 1536 + warp * 64;
    uint4 vreg[4];
    uint32_t vsw[4];
    #pragma unroll
    for (int i = 0; i < 4; i++) {
        int idx = lane + i * 32;           // 0..127
        int r = idx >> 3, c8 = idx & 7;
        const __half* src = base + (size_t)r * 1536 + c8 * 8;
        uint32_t off = (uint32_t)(r * 128 + c8 * 16);
        uint32_t sw = off ^ ((off >> 3) & 0x70);
        *(uint4*)(sq + sw) = *(const uint4*)(src);
        *(uint4*)(sk + sw) = *(const uint4*)(src + 512);
        vreg[i] = *(const uint4*)(src + 1024);
        vsw[i] = sw;
    }
    __syncwarp();

    const int mid = lane >> 3, r7 = lane & 7;
    const int g = lane >> 2, q = lane & 3;
    const uint32_t sqb = smem_u32(sq), skb = smem_u32(sk);
    const uint32_t arow = (uint32_t)((mid & 1) * 8 + r7);
    const uint32_t acolb = (uint32_t)((mid >> 1) * 16);
    const uint32_t brow = (uint32_t)((mid >> 1) * 8 + r7);
    const uint32_t bcolb = (uint32_t)((mid & 1) * 16);
    const uint32_t axor = (uint32_t)(r7 << 4);

    // ---- S = Q K^T ----
    float s0[4] = {0.f, 0.f, 0.f, 0.f};
    float s1[4] = {0.f, 0.f, 0.f, 0.f};
    #pragma unroll
    for (int kk = 0; kk < 4; kk++) {
        uint32_t a[4], b[4];
        ldsm_x4(a, sqb + (arow << 7) + ((acolb + kk * 32) ^ axor));
        ldsm_x4(b, skb + (brow << 7) + ((bcolb + kk * 32) ^ axor));
        mma_fp16(s0, a, b);
        mma_fp16(s1, a, b + 2);
    }
    // Q fragments consumed -> reuse sq for V
    #pragma unroll
    for (int i = 0; i < 4; i++)
        *(uint4*)(sq + vsw[i]) = vreg[i];

    // ---- softmax (rows g and g+8; deferred normalization) ----
    float e0[4], e1[4], inv[2];
    #pragma unroll
    for (int h2 = 0; h2 < 2; h2++) {
        const int i0 = h2 * 2, i1 = h2 * 2 + 1;
        float a0 = s0[i0] * SCALE, a1 = s0[i1] * SCALE;
        float b0 = s1[i0] * SCALE, b1 = s1[i1] * SCALE;
        float m = fmaxf(fmaxf(a0, a1), fmaxf(b0, b1));
        m = fmaxf(m, __shfl_xor_sync(0xffffffffu, m, 1));
        m = fmaxf(m, __shfl_xor_sync(0xffffffffu, m, 2));
        a0 = expf(a0 - m); a1 = expf(a1 - m);
        b0 = expf(b0 - m); b1 = expf(b1 - m);
        float su = a0 + a1 + b0 + b1;
        su += __shfl_xor_sync(0xffffffffu, su, 1);
        su += __shfl_xor_sync(0xffffffffu, su, 2);
        inv[h2] = __frcp_rn(su);
        e0[i0] = a0; e0[i1] = a1;
        e1[i0] = b0; e1[i1] = b1;
    }

    uint32_t pa[4];
    pa[0] = pack_h2(e0[0], e0[1]);
    pa[1] = pack_h2(e0[2], e0[3]);
    pa[2] = pack_h2(e1[0], e1[1]);
    pa[3] = pack_h2(e1[2], e1[3]);
    __syncwarp();

    // ---- O = P~ V ----
    float o[8][4];
    #pragma unroll
    for (int u = 0; u < 8; u++)
        #pragma unroll
        for (int r = 0; r < 4; r++) o[u][r] = 0.f;
    #pragma unroll
    for (int nt = 0; nt < 4; nt++) {
        uint32_t b[4];
        ldsm_x4_t(b, sqb + (arow << 7) + ((acolb + nt * 32) ^ axor));
        mma_fp16(o[nt * 2 + 0], pa, b);
        mma_fp16(o[nt * 2 + 1], pa, b + 2);
    }

    __half* dst = xh + (size_t)widx * 16 * 512 + warp * 64;
    #pragma unroll
    for (int u = 0; u < 8; u++) {
        const int col = u * 8 + 2 * q;
        *(uint32_t*)(dst + (size_t)g * 512 + col) =
            pack_h2(o[u][0] * inv[0], o[u][1] * inv[0]);
        *(uint32_t*)(dst + (size_t)(g + 8) * 512 + col) =
            pack_h2(o[u][2] * inv[1], o[u][3] * inv[1]);
    }
}

// ---------------- launch ---------------------------------------------------
#define TC_SMEM (NPIPE * STG_BYTES)   // 98304 bytes
#define QKV_ROWS (NTOK / GBM)         // 392
#define VL_ROWS  ((NWIN + GBM - 1) / GBM)   // 25

extern "C" void kernel_launch(void* const* d_in, const int* in_sizes, int n_in,
                              void* d_out, int out_size) {
    const float* x        = (const float*)d_in[0];
    const float* w_qkv_h  = (const float*)d_in[1];
    const float* w_qkv_l  = (const float*)d_in[2];
    const float* w_proj   = (const float*)d_in[3];
    const float* b_proj   = (const float*)d_in[4];
    float* out = (float*)d_out;

    __half *qkv, *xg, *xh, *xavg, *vl, *wqkv, *wvl, *wp1, *wp2;
    float *yl;
    int* ridx;
    cudaGetSymbolAddress((void**)&qkv,  g_qkv);
    cudaGetSymbolAddress((void**)&xg,   g_xg);
    cudaGetSymbolAddress((void**)&xh,   g_xh);
    cudaGetSymbolAddress((void**)&xavg, g_xavg);
    cudaGetSymbolAddress((void**)&vl,   g_vl);
    cudaGetSymbolAddress((void**)&yl,   g_yl);
    cudaGetSymbolAddress((void**)&wqkv, g_wqkv);
    cudaGetSymbolAddress((void**)&wvl,  g_wvl);
    cudaGetSymbolAddress((void**)&wp1,  g_wp1);
    cudaGetSymbolAddress((void**)&wp2,  g_wp2);
    cudaGetSymbolAddress((void**)&ridx, g_rowidx);

    cudaFuncSetAttribute(tc_gemm, cudaFuncAttributeMaxDynamicSharedMemorySize, TC_SMEM);
    cudaFuncSetAttribute(tc_gemm_dual, cudaFuncAttributeMaxDynamicSharedMemorySize, TC_SMEM);
    cudaFuncSetAttribute(k_attn_tc, cudaFuncAttributeMaxDynamicSharedMemorySize, ATT_SMEM);

    // 1. fused prep: gather + pool + rowidx + weight conversion (one launch)
    k_prep<<<NWIN + WPREP_BLKS, 128>>>(x, w_qkv_h, w_qkv_l, w_proj,
                                       xg, xavg, ridx, wqkv, wvl, wp1, wp2);

    // 2. merged launch: qkv = xg @ wqkv^T (rows < 392)  +  vl = xavg @ wvl^T
    //    (rows >= 392; vl CTAs fill the qkv wave tail)
    tc_gemm_dual<<<dim3(1536 / GBN, QKV_ROWS + VL_ROWS), 128, TC_SMEM>>>(
        xg, wqkv, qkv, 1536, NTOK, 1,
        xavg, wvl, vl, 512, NWIN, 1,
        QKV_ROWS, 512 / GBN);

    // 3. yl = vl @ Wp2^T  (fp32 out)
    tc_gemm<<<dim3(512 / GBN, VL_ROWS), 128, TC_SMEM>>>(
        vl, wp2, yl, 512, nullptr, nullptr, nullptr, NWIN, 0);

    // 4. tensor-core window attention (block = window, warp = head)
    k_attn_tc<<<NWIN, 256, ATT_SMEM>>>(qkv, xh);

    // 5. out = scatter( xh @ Wp1^T + yl[window] + bias )  (fp32 out)
    tc_gemm<<<dim3(512 / GBN, NTOK / GBM), 128, TC_SMEM>>>(
        xh, wp1, out, 512, ridx, yl, b_proj, NTOK, 0);
}

// round 15
// speedup vs baseline: 1.0296x; 1.0179x over previous
#include <cuda_runtime.h>
#include <cuda_fp16.h>
#include <math.h>
#include <stdint.h>

// Problem constants
#define B_DIM 16
#define H_DIM 56
#define W_DIM 56
#define C_DIM 512
#define NHEAD 8
#define HD 64
#define WS 4
#define NWIN 3136      // 16 * 14 * 14
#define NTOK 50176     // NWIN * 16
#define SCALE 0.04419417382415922f   // 512^-0.5

// ---------------- scratch (static device globals; no allocation) -----------
__device__ __half g_qkv[(size_t)NTOK * 1536]; // qkv of local branch (fp16)
__device__ __half g_xg[(size_t)NTOK * 512];   // gathered x (fp16)
__device__ __half g_xh[(size_t)NTOK * 512];   // local attention out (fp16)
__device__ __half g_xavg[NWIN * 512];         // pooled window tokens (fp16)
__device__ __half g_vl[NWIN * 512];           // v of global branch (fp16)
__device__ float  g_yl[NWIN * 512];           // vl @ Wp2^T (fp32 window add)
__device__ __half g_wqkv[1536 * 512];         // fp16 w_qkv_h
__device__ __half g_wvl[512 * 512];           // fp16 w_qkv_l v-part
__device__ __half g_wp1[512 * 512];           // fp16 w_proj[:, :512]
__device__ __half g_wp2[512 * 512];           // fp16 w_proj[:, 512:]
__device__ int    g_rowidx[NTOK];             // gt -> token row in x / out

// ---------------- small helpers --------------------------------------------
__device__ __forceinline__ uint32_t smem_u32(const void* p) {
    uint32_t a;
    asm("{ .reg .u64 t; cvta.to.shared.u64 t, %1; cvt.u32.u64 %0, t; }" : "=r"(a) : "l"(p));
    return a;
}

__device__ __forceinline__ void cpasync16(uint32_t dst, const void* src) {
    asm volatile("cp.async.cg.shared.global [%0], [%1], 16;" :: "r"(dst), "l"(src) : "memory");
}

__device__ __forceinline__ void ldsm_x4(uint32_t r[4], uint32_t addr) {
    asm volatile("ldmatrix.sync.aligned.m8n8.x4.shared.b16 {%0,%1,%2,%3}, [%4];"
                 : "=r"(r[0]), "=r"(r[1]), "=r"(r[2]), "=r"(r[3]) : "r"(addr));
}

__device__ __forceinline__ void ldsm_x4_t(uint32_t r[4], uint32_t addr) {
    asm volatile("ldmatrix.sync.aligned.m8n8.x4.trans.shared.b16 {%0,%1,%2,%3}, [%4];"
                 : "=r"(r[0]), "=r"(r[1]), "=r"(r[2]), "=r"(r[3]) : "r"(addr));
}

__device__ __forceinline__ void mma_fp16(float c[4], const uint32_t a[4], const uint32_t b[2]) {
    asm volatile(
        "mma.sync.aligned.m16n8k16.row.col.f32.f16.f16.f32 "
        "{%0,%1,%2,%3}, {%4,%5,%6,%7}, {%8,%9}, {%0,%1,%2,%3};"
        : "+f"(c[0]), "+f"(c[1]), "+f"(c[2]), "+f"(c[3])
        : "r"(a[0]), "r"(a[1]), "r"(a[2]), "r"(a[3]), "r"(b[0]), "r"(b[1]));
}

__device__ __forceinline__ uint32_t pack_h2(float a, float b) {
    __half2 h = __floats2half2_rn(a, b);
    return *(uint32_t*)&h;
}

// ---------------- fused prep: gather + pool + rowidx + weight convert ------
#define WPREP_BLKS 320
#define WTOTAL (196608 + 65536 + 65536)    // float4 units

__global__ __launch_bounds__(128)
void k_prep(const float* __restrict__ x,
            const float* __restrict__ wqkvh, const float* __restrict__ wqkvl,
            const float* __restrict__ wproj,
            __half* __restrict__ xg, __half* __restrict__ xavg,
            int* __restrict__ ridx,
            __half* __restrict__ wqkv, __half* __restrict__ wvl,
            __half* __restrict__ wp1, __half* __restrict__ wp2) {
    if (blockIdx.x >= NWIN) {
        const int base = (blockIdx.x - NWIN) * 128 + threadIdx.x;
        for (int i = base; i < WTOTAL; i += WPREP_BLKS * 128) {
            if (i < 196608) {
                float4 v = *(const float4*)(wqkvh + (size_t)i * 4);
                *(uint2*)(wqkv + (size_t)i * 4) =
                    make_uint2(pack_h2(v.x, v.y), pack_h2(v.z, v.w));
            } else if (i < 262144) {
                int j = i - 196608;
                float4 v = *(const float4*)(wqkvl + (size_t)(1024 * 512) + (size_t)j * 4);
                *(uint2*)(wvl + (size_t)j * 4) =
                    make_uint2(pack_h2(v.x, v.y), pack_h2(v.z, v.w));
            } else {
                int j = i - 262144;
                int n = j >> 7, k4 = (j & 127) * 4;
                float4 a = *(const float4*)(wproj + (size_t)n * 1024 + k4);
                float4 b = *(const float4*)(wproj + (size_t)n * 1024 + 512 + k4);
                *(uint2*)(wp1 + (size_t)n * 512 + k4) =
                    make_uint2(pack_h2(a.x, a.y), pack_h2(a.z, a.w));
                *(uint2*)(wp2 + (size_t)n * 512 + k4) =
                    make_uint2(pack_h2(b.x, b.y), pack_h2(b.z, b.w));
            }
        }
        return;
    }

    const int widx = blockIdx.x;
    const int b = widx / 196;
    const int rem = widx % 196;
    const int wh = rem / 14, ww = rem % 14;
    const int c = threadIdx.x * 4;

    if (threadIdx.x < 16) {
        const int t = threadIdx.x;
        const int row = wh * WS + (t >> 2);
        const int col = ww * WS + (t & 3);
        ridx[widx * 16 + t] = (b * H_DIM + row) * W_DIM + col;
    }

    float4 s = make_float4(0.f, 0.f, 0.f, 0.f);
    #pragma unroll
    for (int t = 0; t < 16; t++) {
        const int row = wh * WS + (t >> 2);
        const int col = ww * WS + (t & 3);
        const size_t srow = (size_t)((b * H_DIM + row) * W_DIM + col);
        const float4 v = *(const float4*)(x + srow * C_DIM + c);
        s.x += v.x; s.y += v.y; s.z += v.z; s.w += v.w;
        *(uint2*)(xg + (size_t)(widx * 16 + t) * C_DIM + c) =
            make_uint2(pack_h2(v.x, v.y), pack_h2(v.z, v.w));
    }
    const float inv = 1.0f / 16.0f;
    *(uint2*)(xavg + (size_t)widx * C_DIM + c) =
        make_uint2(pack_h2(s.x * inv, s.y * inv), pack_h2(s.z * inv, s.w * inv));
}

// ---------------- fp16 tensor GEMM body: C = A * B^T -----------------------
// CTA tile 128x128 with 4 warps (128 threads), warp tile 64x64 (2Mx2N),
// BK=64 halves (128B rows, SW128), 3-stage cp.async pipeline.
#define GBM 128
#define GBN 128
#define GBK 64
#define GK  512
#define NSTG (GK / GBK)        // 8 k-slabs
#define ASTG 16384             // 128 rows * 128 B
#define STG_BYTES 32768        // A + B
#define NPIPE 3

__device__ __forceinline__
void gemm_body(const __half* __restrict__ A, const __half* __restrict__ B,
               void* __restrict__ Cv, int ldc,
               const int* __restrict__ cmap, const float* __restrict__ addwin,
               const float* __restrict__ bias, int M, int outHalf,
               int bm, int bn, char* smem) {
    const uint32_t sbase = smem_u32(smem);

    const int tid  = threadIdx.x;
    const int warp = tid >> 5;
    const int lane = tid & 31;
    const int g = lane >> 2;
    const int q = lane & 3;
    const int wm = (warp >> 1) * 64;     // 2 warps in M
    const int wn = (warp & 1) * 64;      // 2 warps in N

    const int mid = lane >> 3;          // matrix id 0..3
    const int r7  = lane & 7;
    const int aRow0 = wm + (mid & 1) * 8 + r7;       // + t*16
    const int aHalf = (mid >> 1) * 16;               // kb byte offset
    const int bRow0 = wn + (mid >> 1) * 8 + r7;      // + up*16
    const int bHalf = (mid & 1) * 16;

    float acc[4][8][4];
    #pragma unroll
    for (int t = 0; t < 4; t++)
        #pragma unroll
        for (int u = 0; u < 8; u++)
            #pragma unroll
            for (int r = 0; r < 4; r++) acc[t][u][r] = 0.f;

    auto load_stage = [&](int s, int buf) {
        const int k0 = s * GBK;
        const uint32_t ao = sbase + buf * STG_BYTES;
        const uint32_t bo = ao + ASTG;
        #pragma unroll
        for (int i = 0; i < 8; i++) {
            int idx = tid + i * 128;          // 0..1023
            int r = idx >> 3, hc = idx & 7;
            int grow = bm + r; if (grow >= M) grow = M - 1;
            uint32_t off = (uint32_t)(r * 128 + hc * 16);
            cpasync16(ao + (off ^ ((off >> 3) & 0x70)),
                      A + (size_t)grow * GK + k0 + hc * 8);
        }
        #pragma unroll
        for (int i = 0; i < 8; i++) {
            int idx = tid + i * 128;
            int r = idx >> 3, hc = idx & 7;
            uint32_t off = (uint32_t)(r * 128 + hc * 16);
            cpasync16(bo + (off ^ ((off >> 3) & 0x70)),
                      B + (size_t)(bn + r) * GK + k0 + hc * 8);
        }
        asm volatile("cp.async.commit_group;" ::: "memory");
    };

    load_stage(0, 0);
    load_stage(1, 1);
    load_stage(2, 2);

    for (int s = 0; s < NSTG; s++) {
        const int buf = s % NPIPE;
        if (s <= NSTG - 3)      asm volatile("cp.async.wait_group 2;" ::: "memory");
        else if (s == NSTG - 2) asm volatile("cp.async.wait_group 1;" ::: "memory");
        else                    asm volatile("cp.async.wait_group 0;" ::: "memory");
        __syncthreads();

        const uint32_t sA = sbase + buf * STG_BYTES;
        const uint32_t sB = sA + ASTG;

        #pragma unroll
        for (int kk = 0; kk < 4; kk++) {
            const uint32_t acol = (uint32_t)(kk * 32 + aHalf);
            const uint32_t bcol = (uint32_t)(kk * 32 + bHalf);
            uint32_t af[4][4];
            #pragma unroll
            for (int t = 0; t < 4; t++) {
                const uint32_t row = (uint32_t)(aRow0 + t * 16);
                ldsm_x4(af[t], sA + (row << 7) + (((row & 7) << 4) ^ acol));
            }
            uint32_t bf[8][2];
            #pragma unroll
            for (int up = 0; up < 4; up++) {
                uint32_t r4[4];
                const uint32_t row = (uint32_t)(bRow0 + up * 16);
                ldsm_x4(r4, sB + (row << 7) + (((row & 7) << 4) ^ bcol));
                bf[up * 2 + 0][0] = r4[0]; bf[up * 2 + 0][1] = r4[1];
                bf[up * 2 + 1][0] = r4[2]; bf[up * 2 + 1][1] = r4[3];
            }
            #pragma unroll
            for (int t = 0; t < 4; t++)
                #pragma unroll
                for (int u = 0; u < 8; u++)
                    mma_fp16(acc[t][u], af[t], bf[u]);
        }
        __syncthreads();
        if (s + NPIPE < NSTG) load_stage(s + NPIPE, buf);
    }

    // ---- epilogue ----
    #pragma unroll
    for (int t = 0; t < 4; t++) {
        #pragma unroll
        for (int half = 0; half < 2; half++) {
            const int gm = bm + wm + t * 16 + g + half * 8;
            if (gm >= M) continue;
            const size_t orow = cmap ? (size_t)cmap[gm] : (size_t)gm;
            const float* ap = addwin ? addwin + (size_t)(gm >> 4) * 512 : nullptr;
            const int colb = bn + wn + 2 * q;
            #pragma unroll
            for (int u = 0; u < 8; u++) {
                const int col = colb + u * 8;
                float o0 = acc[t][u][half * 2 + 0];
                float o1 = acc[t][u][half * 2 + 1];
                if (ap)   { o0 += ap[col];   o1 += ap[col + 1]; }
                if (bias) { o0 += bias[col]; o1 += bias[col + 1]; }
                if (outHalf) {
                    *(uint32_t*)((__half*)Cv + orow * ldc + col) = pack_h2(o0, o1);
                } else {
                    *(float2*)((float*)Cv + orow * ldc + col) = make_float2(o0, o1);
                }
            }
        }
    }
}

// standard single-task wrapper
__global__ __launch_bounds__(128, 2)
void tc_gemm(const __half* __restrict__ A, const __half* __restrict__ B,
             void* __restrict__ Cv, int ldc,
             const int* __restrict__ cmap, const float* __restrict__ addwin,
             const float* __restrict__ bias, int M, int outHalf) {
    extern __shared__ char smem[];
    gemm_body(A, B, Cv, ldc, cmap, addwin, bias, M, outHalf,
              blockIdx.y * GBM, blockIdx.x * GBN, smem);
}

// dual-task wrapper: rows [0, ySplit) -> task 1; rows >= ySplit -> task 2
__global__ __launch_bounds__(128, 2)
void tc_gemm_dual(const __half* __restrict__ A1, const __half* __restrict__ B1,
                  void* __restrict__ C1, int ldc1, int M1, int outHalf1,
                  const __half* __restrict__ A2, const __half* __restrict__ B2,
                  void* __restrict__ C2, int ldc2, int M2, int outHalf2,
                  int ySplit, int x2lim) {
    extern __shared__ char smem[];
    if ((int)blockIdx.y < ySplit) {
        gemm_body(A1, B1, C1, ldc1, nullptr, nullptr, nullptr, M1, outHalf1,
                  blockIdx.y * GBM, blockIdx.x * GBN, smem);
    } else {
        if ((int)blockIdx.x >= x2lim) return;
        gemm_body(A2, B2, C2, ldc2, nullptr, nullptr, nullptr, M2, outHalf2,
                  (blockIdx.y - ySplit) * GBM, blockIdx.x * GBN, smem);
    }
}

// ---------------- tensor-core window attention -----------------------------
// block = 1 window (256 threads), warp = 1 head. No block-wide syncs.
#define AWARP_B 4096                       // bytes per warp (Q + K tiles)
#define ATT_SMEM (8 * AWARP_B)             // 32768 bytes

__global__ __launch_bounds__(256)
void k_attn_tc(const __half* __restrict__ qkv, __half* __restrict__ xh) {
    extern __shared__ char asm_b[];
    const int widx = blockIdx.x;
    const int warp = threadIdx.x >> 5;     // head
    const int lane = threadIdx.x & 31;

    char* sq = asm_b + warp * AWARP_B;     // 2048 B swizzled tile
    char* sk = sq + 2048;

    const __half* base = qkv + (size_t)widx * 16 * 1536 + warp * 64;
    uint4 vreg[4];
    uint32_t vsw[4];
    #pragma unroll
    for (int i = 0; i < 4; i++) {
        int idx = lane + i * 32;           // 0..127
        int r = idx >> 3, c8 = idx & 7;
        const __half* src = base + (size_t)r * 1536 + c8 * 8;
        uint32_t off = (uint32_t)(r * 128 + c8 * 16);
        uint32_t sw = off ^ ((off >> 3) & 0x70);
        *(uint4*)(sq + sw) = *(const uint4*)(src);
        *(uint4*)(sk + sw) = *(const uint4*)(src + 512);
        vreg[i] = *(const uint4*)(src + 1024);
        vsw[i] = sw;
    }
    __syncwarp();

    const int mid = lane >> 3, r7 = lane & 7;
    const int g = lane >> 2, q = lane & 3;
    const uint32_t sqb = smem_u32(sq), skb = smem_u32(sk);
    const uint32_t arow = (uint32_t)((mid & 1) * 8 + r7);
    const uint32_t acolb = (uint32_t)((mid >> 1) * 16);
    const uint32_t brow = (uint32_t)((mid >> 1) * 8 + r7);
    const uint32_t bcolb = (uint32_t)((mid & 1) * 16);
    const uint32_t axor = (uint32_t)(r7 << 4);

    // ---- S = Q K^T ----
    float s0[4] = {0.f, 0.f, 0.f, 0.f};
    float s1[4] = {0.f, 0.f, 0.f, 0.f};
    #pragma unroll
    for (int kk = 0; kk < 4; kk++) {
        uint32_t a[4], b[4];
        ldsm_x4(a, sqb + (arow << 7) + ((acolb + kk * 32) ^ axor));
        ldsm_x4(b, skb + (brow << 7) + ((bcolb + kk * 32) ^ axor));
        mma_fp16(s0, a, b);
        mma_fp16(s1, a, b + 2);
    }
    // Q fragments consumed -> reuse sq for V
    #pragma unroll
    for (int i = 0; i < 4; i++)
        *(uint4*)(sq + vsw[i]) = vreg[i];

    // ---- softmax (rows g and g+8; deferred normalization) ----
    float e0[4], e1[4], inv[2];
    #pragma unroll
    for (int h2 = 0; h2 < 2; h2++) {
        const int i0 = h2 * 2, i1 = h2 * 2 + 1;
        float a0 = s0[i0] * SCALE, a1 = s0[i1] * SCALE;
        float b0 = s1[i0] * SCALE, b1 = s1[i1] * SCALE;
        float m = fmaxf(fmaxf(a0, a1), fmaxf(b0, b1));
        m = fmaxf(m, __shfl_xor_sync(0xffffffffu, m, 1));
        m = fmaxf(m, __shfl_xor_sync(0xffffffffu, m, 2));
        a0 = expf(a0 - m); a1 = expf(a1 - m);
        b0 = expf(b0 - m); b1 = expf(b1 - m);
        float su = a0 + a1 + b0 + b1;
        su += __shfl_xor_sync(0xffffffffu, su, 1);
        su += __shfl_xor_sync(0xffffffffu, su, 2);
        inv[h2] = __frcp_rn(su);
        e0[i0] = a0; e0[i1] = a1;
        e1[i0] = b0; e1[i1] = b1;
    }

    uint32_t pa[4];
    pa[0] = pack_h2(e0[0], e0[1]);
    pa[1] = pack_h2(e0[2], e0[3]);
    pa[2] = pack_h2(e1[0], e1[1]);
    pa[3] = pack_h2(e1[2], e1[3]);
    __syncwarp();

    // ---- O = P~ V ----
    float o[8][4];
    #pragma unroll
    for (int u = 0; u < 8; u++)
        #pragma unroll
        for (int r = 0; r < 4; r++) o[u][r] = 0.f;
    #pragma unroll
    for (int nt = 0; nt < 4; nt++) {
        uint32_t b[4];
        ldsm_x4_t(b, sqb + (arow << 7) + ((acolb + nt * 32) ^ axor));
        mma_fp16(o[nt * 2 + 0], pa, b);
        mma_fp16(o[nt * 2 + 1], pa, b + 2);
    }

    __half* dst = xh + (size_t)widx * 16 * 512 + warp * 64;
    #pragma unroll
    for (int u = 0; u < 8; u++) {
        const int col = u * 8 + 2 * q;
        *(uint32_t*)(dst + (size_t)g * 512 + col) =
            pack_h2(o[u][0] * inv[0], o[u][1] * inv[0]);
        *(uint32_t*)(dst + (size_t)(g + 8) * 512 + col) =
            pack_h2(o[u][2] * inv[1], o[u][3] * inv[1]);
    }
}

// ---------------- launch ---------------------------------------------------
#define TC_SMEM (NPIPE * STG_BYTES)   // 98304 bytes
#define QKV_ROWS (NTOK / GBM)         // 392
#define VL_ROWS  ((NWIN + GBM - 1) / GBM)   // 25

extern "C" void kernel_launch(void* const* d_in, const int* in_sizes, int n_in,
                              void* d_out, int out_size) {
    const float* x        = (const float*)d_in[0];
    const float* w_qkv_h  = (const float*)d_in[1];
    const float* w_qkv_l  = (const float*)d_in[2];
    const float* w_proj   = (const float*)d_in[3];
    const float* b_proj   = (const float*)d_in[4];
    float* out = (float*)d_out;

    __half *qkv, *xg, *xh, *xavg, *vl, *wqkv, *wvl, *wp1, *wp2;
    float *yl;
    int* ridx;
    cudaGetSymbolAddress((void**)&qkv,  g_qkv);
    cudaGetSymbolAddress((void**)&xg,   g_xg);
    cudaGetSymbolAddress((void**)&xh,   g_xh);
    cudaGetSymbolAddress((void**)&xavg, g_xavg);
    cudaGetSymbolAddress((void**)&vl,   g_vl);
    cudaGetSymbolAddress((void**)&yl,   g_yl);
    cudaGetSymbolAddress((void**)&wqkv, g_wqkv);
    cudaGetSymbolAddress((void**)&wvl,  g_wvl);
    cudaGetSymbolAddress((void**)&wp1,  g_wp1);
    cudaGetSymbolAddress((void**)&wp2,  g_wp2);
    cudaGetSymbolAddress((void**)&ridx, g_rowidx);

    cudaFuncSetAttribute(tc_gemm, cudaFuncAttributeMaxDynamicSharedMemorySize, TC_SMEM);
    cudaFuncSetAttribute(tc_gemm_dual, cudaFuncAttributeMaxDynamicSharedMemorySize, TC_SMEM);
    cudaFuncSetAttribute(k_attn_tc, cudaFuncAttributeMaxDynamicSharedMemorySize, ATT_SMEM);

    // side stream + fork/join events (created per call; host-side objects)
    cudaStream_t s2;
    cudaEvent_t eFork, eJoin;
    cudaStreamCreateWithFlags(&s2, cudaStreamNonBlocking);
    cudaEventCreateWithFlags(&eFork, cudaEventDisableTiming);
    cudaEventCreateWithFlags(&eJoin, cudaEventDisableTiming);

    // 1. fused prep: gather + pool + rowidx + weight conversion (one launch)
    k_prep<<<NWIN + WPREP_BLKS, 128>>>(x, w_qkv_h, w_qkv_l, w_proj,
                                       xg, xavg, ridx, wqkv, wvl, wp1, wp2);

    // 2. merged launch: qkv = xg @ wqkv^T (rows < 392)  +  vl = xavg @ wvl^T
    tc_gemm_dual<<<dim3(1536 / GBN, QKV_ROWS + VL_ROWS), 128, TC_SMEM>>>(
        xg, wqkv, qkv, 1536, NTOK, 1,
        xavg, wvl, vl, 512, NWIN, 1,
        QKV_ROWS, 512 / GBN);

    // fork: yl = vl @ Wp2^T on side stream, concurrent with attention
    cudaEventRecord(eFork, 0);
    cudaStreamWaitEvent(s2, eFork, 0);
    tc_gemm<<<dim3(512 / GBN, VL_ROWS), 128, TC_SMEM, s2>>>(
        vl, wp2, yl, 512, nullptr, nullptr, nullptr, NWIN, 0);
    cudaEventRecord(eJoin, s2);

    // 3. tensor-core window attention (main stream, overlaps yl)
    k_attn_tc<<<NWIN, 256, ATT_SMEM>>>(qkv, xh);

    // join: proj needs both xh (main stream) and yl (side stream)
    cudaStreamWaitEvent(0, eJoin, 0);

    // 4. out = scatter( xh @ Wp1^T + yl[window] + bias )  (fp32 out)
    tc_gemm<<<dim3(512 / GBN, NTOK / GBM), 128, TC_SMEM>>>(
        xh, wp1, out, 512, ridx, yl, b_proj, NTOK, 0);
}